// round 2
// baseline (speedup 1.0000x reference)
#include <cuda_runtime.h>
#include <math.h>

// ---------------------------------------------------------------------------
// SelectiveAttention: x = OutProj(softmax((Q Wq + bq)*s @ (K Wk + bk)^T) @ (V Wv + bv))
// Output tuple: (x [2048,4,1024], attn [64,2048,2048]) concatenated, fp32.
// Round 1: full fp32, classic 128x128 register-tiled SGEMMs. Correctness +
// tolerance calibration baseline.
// ---------------------------------------------------------------------------

constexpr int TQ  = 2048;
constexpr int TK  = 2048;
constexpr int BSZ = 4;
constexpr int CDIM = 1024;
constexpr int H   = 16;
constexpr int DH  = 64;
constexpr int BH  = BSZ * H;          // 64
constexpr int MPROJ = TQ * BSZ;       // 8192

// Scratch (device globals — no allocation allowed in kernel_launch)
__device__ float g_q[(size_t)BH * TQ * DH];   // [bh, t, d]
__device__ float g_k[(size_t)BH * TK * DH];
__device__ float g_v[(size_t)BH * TK * DH];
__device__ float g_x[(size_t)BH * TQ * DH];

// ---------------------------------------------------------------------------
// Generic 128x128x16 fp32 tiled GEMM over K=1024.
// MODE 0/1/2: projections q/k/v -> scatter to [bh, t, d] layout (scale applied)
// MODE 3   : output projection, A gathered from g_x, linear output + bias
// ---------------------------------------------------------------------------
template<int MODE>
__global__ __launch_bounds__(256, 2)
void gemm1024_kernel(const float* __restrict__ A, const float* __restrict__ W,
                     const float* __restrict__ bias, float* __restrict__ Out,
                     float scale)
{
    __shared__ float As[16 * 132];   // As[k][m], padded row 132
    __shared__ float Bs[16 * 132];   // Bs[k][n], padded row 132

    const int tid = threadIdx.x;          // 256 threads
    const int bx  = blockIdx.x;           // N tile (8)
    const int by  = blockIdx.y;           // M tile (64)
    const int tx  = tid & 15;
    const int ty  = tid >> 4;
    const int m0  = by * 128;
    const int n0  = bx * 128;

    float acc[8][8];
#pragma unroll
    for (int i = 0; i < 8; i++)
#pragma unroll
        for (int j = 0; j < 8; j++) acc[i][j] = 0.f;

    for (int k0 = 0; k0 < CDIM; k0 += 16) {
        // ---- load A tile (128 rows x 16 k), store transposed As[k][m]
#pragma unroll
        for (int i = 0; i < 2; i++) {
            int li = tid + i * 256;
            int r  = li >> 2;          // 0..127
            int c  = li & 3;           // float4 index within row
            float4 a;
            if (MODE < 3) {
                a = *(const float4*)&A[(size_t)(m0 + r) * CDIM + k0 + c * 4];
            } else {
                // gather from g_x [bh, t, d]; m = t*BSZ + b
                int m = m0 + r;
                int t = m >> 2, b = m & 3;
                int k = k0 + c * 4;
                int h = k >> 6, d = k & 63;
                a = *(const float4*)&g_x[(((size_t)(b * H + h)) * TQ + t) * DH + d];
            }
            float* dst = &As[r];
            dst[(c * 4 + 0) * 132] = a.x;
            dst[(c * 4 + 1) * 132] = a.y;
            dst[(c * 4 + 2) * 132] = a.z;
            dst[(c * 4 + 3) * 132] = a.w;
        }
        // ---- load B tile (16 k x 128 n), direct Bs[k][n]
#pragma unroll
        for (int i = 0; i < 2; i++) {
            int li = tid + i * 256;
            int r  = li >> 5;          // 0..15
            int c  = li & 31;          // float4 within row
            float4 b = *(const float4*)&W[(size_t)(k0 + r) * CDIM + n0 + c * 4];
            *(float4*)&Bs[r * 132 + c * 4] = b;
        }
        __syncthreads();

#pragma unroll
        for (int kk = 0; kk < 16; kk++) {
            float4 a0 = *(const float4*)&As[kk * 132 + ty * 4];
            float4 a1 = *(const float4*)&As[kk * 132 + 64 + ty * 4];
            float4 b0 = *(const float4*)&Bs[kk * 132 + tx * 4];
            float4 b1 = *(const float4*)&Bs[kk * 132 + 64 + tx * 4];
            float a[8] = {a0.x, a0.y, a0.z, a0.w, a1.x, a1.y, a1.z, a1.w};
            float b[8] = {b0.x, b0.y, b0.z, b0.w, b1.x, b1.y, b1.z, b1.w};
#pragma unroll
            for (int i = 0; i < 8; i++)
#pragma unroll
                for (int j = 0; j < 8; j++) acc[i][j] += a[i] * b[j];
        }
        __syncthreads();
    }

    // ---- epilogue
#pragma unroll
    for (int i = 0; i < 8; i++) {
        int m = m0 + ((i < 4) ? (ty * 4 + i) : (64 + ty * 4 + i - 4));
#pragma unroll
        for (int jc = 0; jc < 2; jc++) {
            int n = n0 + jc * 64 + tx * 4;
            float4 v;
            v.x = (acc[i][jc * 4 + 0] + bias[n + 0]) * scale;
            v.y = (acc[i][jc * 4 + 1] + bias[n + 1]) * scale;
            v.z = (acc[i][jc * 4 + 2] + bias[n + 2]) * scale;
            v.w = (acc[i][jc * 4 + 3] + bias[n + 3]) * scale;
            if (MODE < 3) {
                int t = m >> 2, b = m & 3;
                int h = n >> 6, d = n & 63;
                float* dst = (MODE == 0) ? g_q : (MODE == 1) ? g_k : g_v;
                *(float4*)&dst[(((size_t)(b * H + h)) * TQ + t) * DH + d] = v;
            } else {
                *(float4*)&Out[(size_t)m * CDIM + n] = v;
            }
        }
    }
}

// ---------------------------------------------------------------------------
// Scores: S[bh] = q[bh] @ k[bh]^T   (M=N=2048, K=64), raw scores -> attn buf
// ---------------------------------------------------------------------------
__global__ __launch_bounds__(256, 2)
void score_kernel(float* __restrict__ attn)
{
    __shared__ float As[16 * 132];   // As[k][m]
    __shared__ float Bs[16 * 132];   // Bs[k][n]

    const int tid = threadIdx.x;
    const int bx  = blockIdx.x;      // N tile (16)
    const int by  = blockIdx.y;      // M tile (16)
    const int bh  = blockIdx.z;      // 64
    const int tx  = tid & 15;
    const int ty  = tid >> 4;
    const int m0  = by * 128;
    const int n0  = bx * 128;

    const float* qp = g_q + (size_t)bh * TQ * DH;
    const float* kp = g_k + (size_t)bh * TK * DH;

    float acc[8][8];
#pragma unroll
    for (int i = 0; i < 8; i++)
#pragma unroll
        for (int j = 0; j < 8; j++) acc[i][j] = 0.f;

    for (int k0 = 0; k0 < DH; k0 += 16) {
#pragma unroll
        for (int i = 0; i < 2; i++) {
            int li = tid + i * 256;
            int r  = li >> 2;
            int c  = li & 3;
            float4 a = *(const float4*)&qp[(size_t)(m0 + r) * DH + k0 + c * 4];
            float* dst = &As[r];
            dst[(c * 4 + 0) * 132] = a.x;
            dst[(c * 4 + 1) * 132] = a.y;
            dst[(c * 4 + 2) * 132] = a.z;
            dst[(c * 4 + 3) * 132] = a.w;
            float4 b = *(const float4*)&kp[(size_t)(n0 + r) * DH + k0 + c * 4];
            float* dstb = &Bs[r];
            dstb[(c * 4 + 0) * 132] = b.x;
            dstb[(c * 4 + 1) * 132] = b.y;
            dstb[(c * 4 + 2) * 132] = b.z;
            dstb[(c * 4 + 3) * 132] = b.w;
        }
        __syncthreads();
#pragma unroll
        for (int kk = 0; kk < 16; kk++) {
            float4 a0 = *(const float4*)&As[kk * 132 + ty * 4];
            float4 a1 = *(const float4*)&As[kk * 132 + 64 + ty * 4];
            float4 b0 = *(const float4*)&Bs[kk * 132 + tx * 4];
            float4 b1 = *(const float4*)&Bs[kk * 132 + 64 + tx * 4];
            float a[8] = {a0.x, a0.y, a0.z, a0.w, a1.x, a1.y, a1.z, a1.w};
            float b[8] = {b0.x, b0.y, b0.z, b0.w, b1.x, b1.y, b1.z, b1.w};
#pragma unroll
            for (int i = 0; i < 8; i++)
#pragma unroll
                for (int j = 0; j < 8; j++) acc[i][j] += a[i] * b[j];
        }
        __syncthreads();
    }

    float* srow = attn + (size_t)bh * TQ * TK;
#pragma unroll
    for (int i = 0; i < 8; i++) {
        int m = m0 + ((i < 4) ? (ty * 4 + i) : (64 + ty * 4 + i - 4));
#pragma unroll
        for (int jc = 0; jc < 2; jc++) {
            int n = n0 + jc * 64 + tx * 4;
            float4 v = make_float4(acc[i][jc * 4 + 0], acc[i][jc * 4 + 1],
                                   acc[i][jc * 4 + 2], acc[i][jc * 4 + 3]);
            *(float4*)&srow[(size_t)m * TK + n] = v;
        }
    }
}

// ---------------------------------------------------------------------------
// Row softmax in-place over attn [BH*TQ rows, TK cols], with key padding mask
// ---------------------------------------------------------------------------
__global__ __launch_bounds__(256)
void softmax_kernel(float* __restrict__ attn, const unsigned char* __restrict__ mask)
{
    const size_t row = blockIdx.x;                // 0 .. BH*TQ-1
    const int bh = (int)(row / TQ);
    const int b  = bh / H;
    float* p = attn + row * (size_t)TK;
    const unsigned char* mrow = mask + (size_t)b * TK;

    const int tid = threadIdx.x;
    float vals[8];
    float mx = -INFINITY;
#pragma unroll
    for (int i = 0; i < 8; i++) {
        int idx = tid + i * 256;
        float v = p[idx];
        if (mrow[idx]) v = -INFINITY;
        vals[i] = v;
        mx = fmaxf(mx, v);
    }
    // block max reduce
    __shared__ float red[8];
#pragma unroll
    for (int o = 16; o; o >>= 1) mx = fmaxf(mx, __shfl_xor_sync(0xffffffffu, mx, o));
    if ((tid & 31) == 0) red[tid >> 5] = mx;
    __syncthreads();
    if (tid == 0) {
        float m = red[0];
#pragma unroll
        for (int w = 1; w < 8; w++) m = fmaxf(m, red[w]);
        red[0] = m;
    }
    __syncthreads();
    mx = red[0];
    __syncthreads();

    float sum = 0.f;
#pragma unroll
    for (int i = 0; i < 8; i++) {
        float e = __expf(vals[i] - mx);
        vals[i] = e;
        sum += e;
    }
#pragma unroll
    for (int o = 16; o; o >>= 1) sum += __shfl_xor_sync(0xffffffffu, sum, o);
    if ((tid & 31) == 0) red[tid >> 5] = sum;
    __syncthreads();
    if (tid == 0) {
        float s = red[0];
#pragma unroll
        for (int w = 1; w < 8; w++) s += red[w];
        red[0] = s;
    }
    __syncthreads();
    const float inv = 1.f / red[0];

#pragma unroll
    for (int i = 0; i < 8; i++) {
        int idx = tid + i * 256;
        p[idx] = vals[i] * inv;
    }
}

// ---------------------------------------------------------------------------
// AV: x[bh] = attn[bh] @ v[bh]   (M=2048, N=64, K=2048), tile 128x64x16
// ---------------------------------------------------------------------------
__global__ __launch_bounds__(256, 2)
void av_kernel(const float* __restrict__ attn)
{
    __shared__ float As[16 * 132];   // As[k][m]
    __shared__ float Bs[16 * 68];    // Bs[k][n], padded 68

    const int tid = threadIdx.x;
    const int by  = blockIdx.x;      // M tile (16)
    const int bh  = blockIdx.y;      // 64
    const int tx  = tid & 15;
    const int ty  = tid >> 4;
    const int m0  = by * 128;

    const float* ap = attn + (size_t)bh * TQ * TK;
    const float* vp = g_v  + (size_t)bh * TK * DH;

    float acc[8][4];
#pragma unroll
    for (int i = 0; i < 8; i++)
#pragma unroll
        for (int j = 0; j < 4; j++) acc[i][j] = 0.f;

    for (int k0 = 0; k0 < TK; k0 += 16) {
#pragma unroll
        for (int i = 0; i < 2; i++) {
            int li = tid + i * 256;
            int r  = li >> 2;
            int c  = li & 3;
            float4 a = *(const float4*)&ap[(size_t)(m0 + r) * TK + k0 + c * 4];
            float* dst = &As[r];
            dst[(c * 4 + 0) * 132] = a.x;
            dst[(c * 4 + 1) * 132] = a.y;
            dst[(c * 4 + 2) * 132] = a.z;
            dst[(c * 4 + 3) * 132] = a.w;
        }
        {
            int r = tid >> 4;        // 0..15
            int c = tid & 15;        // float4 within 64-wide row
            float4 b = *(const float4*)&vp[(size_t)(k0 + r) * DH + c * 4];
            *(float4*)&Bs[r * 68 + c * 4] = b;
        }
        __syncthreads();
#pragma unroll
        for (int kk = 0; kk < 16; kk++) {
            float4 a0 = *(const float4*)&As[kk * 132 + ty * 4];
            float4 a1 = *(const float4*)&As[kk * 132 + 64 + ty * 4];
            float4 b0 = *(const float4*)&Bs[kk * 68 + tx * 4];
            float a[8] = {a0.x, a0.y, a0.z, a0.w, a1.x, a1.y, a1.z, a1.w};
            float b[4] = {b0.x, b0.y, b0.z, b0.w};
#pragma unroll
            for (int i = 0; i < 8; i++)
#pragma unroll
                for (int j = 0; j < 4; j++) acc[i][j] += a[i] * b[j];
        }
        __syncthreads();
    }

#pragma unroll
    for (int i = 0; i < 8; i++) {
        int m = m0 + ((i < 4) ? (ty * 4 + i) : (64 + ty * 4 + i - 4));
        float4 v = make_float4(acc[i][0], acc[i][1], acc[i][2], acc[i][3]);
        *(float4*)&g_x[(((size_t)bh * TQ) + m) * DH + tx * 4] = v;
    }
}

// ---------------------------------------------------------------------------
extern "C" void kernel_launch(void* const* d_in, const int* in_sizes, int n_in,
                              void* d_out, int out_size)
{
    const float* query = (const float*)d_in[0];
    const float* key   = (const float*)d_in[1];
    const float* value = (const float*)d_in[2];
    const unsigned char* mask = (const unsigned char*)d_in[3];
    const float* Wq = (const float*)d_in[4];
    const float* bq = (const float*)d_in[5];
    const float* Wk = (const float*)d_in[6];
    const float* bk = (const float*)d_in[7];
    const float* Wv = (const float*)d_in[8];
    const float* bv = (const float*)d_in[9];
    const float* Wo = (const float*)d_in[10];
    const float* bo = (const float*)d_in[11];

    float* out_x = (float*)d_out;                             // [2048,4,1024]
    float* attn  = out_x + (size_t)TQ * BSZ * CDIM;           // [64,2048,2048]

    const float scale = 0.125f;   // 1/sqrt(64)

    dim3 blk(256);
    gemm1024_kernel<0><<<dim3(8, 64), blk>>>(query, Wq, bq, nullptr, scale);
    gemm1024_kernel<1><<<dim3(8, 64), blk>>>(key,   Wk, bk, nullptr, 1.f);
    gemm1024_kernel<2><<<dim3(8, 64), blk>>>(value, Wv, bv, nullptr, 1.f);
    score_kernel<<<dim3(16, 16, 64), blk>>>(attn);
    softmax_kernel<<<dim3(BH * TQ), blk>>>(attn, mask);
    av_kernel<<<dim3(16, 64), blk>>>(attn);
    gemm1024_kernel<3><<<dim3(8, 64), blk>>>(nullptr, Wo, bo, out_x, 1.f);
}

// round 3
// speedup vs baseline: 1.4939x; 1.4939x over previous
#include <cuda_runtime.h>
#include <math.h>

// ---------------------------------------------------------------------------
// Round 3: tf32 tensor-core (mma.sync.m16n8k8) everywhere + fused attention.
//   proj(q,k,v) -> rowstats (online softmax stats, S recomputed, no big I/O)
//   -> attn_av (S recomputed, normalized P written ONCE + fused P@V)
//   -> out projection.
// attn buffer traffic: 4.3GB -> 1.07GB. All accumulation fp32.
// ---------------------------------------------------------------------------

constexpr int TQ  = 2048;
constexpr int TK  = 2048;
constexpr int BSZ = 4;
constexpr int CDIM = 1024;
constexpr int H   = 16;
constexpr int DH  = 64;
constexpr int BH  = BSZ * H;   // 64

__device__ float  g_q[(size_t)BH * TQ * DH];
__device__ float  g_k[(size_t)BH * TK * DH];
__device__ float  g_v[(size_t)BH * TK * DH];
__device__ float  g_x[(size_t)BH * TQ * DH];
__device__ float2 g_stats[(size_t)BH * TQ];

__device__ __forceinline__ unsigned f2tf(float x) {
    unsigned r; asm("cvt.rna.tf32.f32 %0, %1;" : "=r"(r) : "f"(x)); return r;
}
__device__ __forceinline__ void mma8(float* d, const unsigned* a, const unsigned* b) {
    asm volatile(
        "mma.sync.aligned.m16n8k8.row.col.f32.tf32.tf32.f32 "
        "{%0,%1,%2,%3},{%4,%5,%6,%7},{%8,%9},{%0,%1,%2,%3};"
        : "+f"(d[0]), "+f"(d[1]), "+f"(d[2]), "+f"(d[3])
        : "r"(a[0]), "r"(a[1]), "r"(a[2]), "r"(a[3]), "r"(b[0]), "r"(b[1]));
}

// ---------------------------------------------------------------------------
// Projection GEMM: C[8192x1024] = A[8192x1024] @ W[1024x1024] (+bias)*scale
// Block tile 128x128, k-step 32. 8 warps: warp grid 2(m) x 4(n), warp 64x32.
// MODE 0/1/2: scatter to g_q/g_k/g_v [bh,t,d]; MODE 3: gather g_x -> Out.
// ---------------------------------------------------------------------------
template<int MODE>
__global__ __launch_bounds__(256)
void proj_kernel(const float* __restrict__ A, const float* __restrict__ W,
                 const float* __restrict__ bias, float* __restrict__ Out,
                 float scale)
{
    __shared__ unsigned As[128 * 36];   // [m][k], row stride 36
    __shared__ unsigned Bs[32 * 136];   // [k][n], row stride 136

    const int tid = threadIdx.x, lane = tid & 31, wid = tid >> 5;
    const int gid = lane >> 2, tig = lane & 3;
    const int wm = wid >> 2, wn = wid & 3;
    const int m0 = blockIdx.y * 128, n0 = blockIdx.x * 128;

    float acc[4][4][4] = {};

    for (int k0 = 0; k0 < CDIM; k0 += 32) {
#pragma unroll
        for (int i = 0; i < 4; i++) {
            int li = tid + i * 256;
            int r = li >> 3, c = li & 7;
            float4 a;
            if (MODE < 3) {
                a = *(const float4*)&A[(size_t)(m0 + r) * CDIM + k0 + c * 4];
            } else {
                int m = m0 + r, t = m >> 2, b = m & 3;
                int k = k0 + c * 4, h = k >> 6, d = k & 63;
                a = *(const float4*)&g_x[(((size_t)(b * H + h)) * TQ + t) * DH + d];
            }
            *(uint4*)&As[r * 36 + c * 4] =
                make_uint4(f2tf(a.x), f2tf(a.y), f2tf(a.z), f2tf(a.w));
        }
#pragma unroll
        for (int i = 0; i < 4; i++) {
            int li = tid + i * 256;
            int r = li >> 5, c = li & 31;
            float4 b = *(const float4*)&W[(size_t)(k0 + r) * CDIM + n0 + c * 4];
            *(uint4*)&Bs[r * 136 + c * 4] =
                make_uint4(f2tf(b.x), f2tf(b.y), f2tf(b.z), f2tf(b.w));
        }
        __syncthreads();

#pragma unroll
        for (int kk = 0; kk < 32; kk += 8) {
            unsigned af[4][4], bf[4][2];
#pragma unroll
            for (int mi = 0; mi < 4; mi++) {
                int rb = wm * 64 + mi * 16;
                af[mi][0] = As[(rb + gid)     * 36 + kk + tig];
                af[mi][1] = As[(rb + gid + 8) * 36 + kk + tig];
                af[mi][2] = As[(rb + gid)     * 36 + kk + tig + 4];
                af[mi][3] = As[(rb + gid + 8) * 36 + kk + tig + 4];
            }
#pragma unroll
            for (int ni = 0; ni < 4; ni++) {
                int cb = wn * 32 + ni * 8;
                bf[ni][0] = Bs[(kk + tig)     * 136 + cb + gid];
                bf[ni][1] = Bs[(kk + tig + 4) * 136 + cb + gid];
            }
#pragma unroll
            for (int mi = 0; mi < 4; mi++)
#pragma unroll
                for (int ni = 0; ni < 4; ni++) mma8(acc[mi][ni], af[mi], bf[ni]);
        }
        __syncthreads();
    }

#pragma unroll
    for (int mi = 0; mi < 4; mi++)
#pragma unroll
        for (int hl = 0; hl < 2; hl++) {
            int m = m0 + wm * 64 + mi * 16 + gid + hl * 8;
#pragma unroll
            for (int ni = 0; ni < 4; ni++) {
                int n = n0 + wn * 32 + ni * 8 + tig * 2;
                float2 v;
                v.x = (acc[mi][ni][hl * 2 + 0] + bias[n + 0]) * scale;
                v.y = (acc[mi][ni][hl * 2 + 1] + bias[n + 1]) * scale;
                if (MODE < 3) {
                    int t = m >> 2, b = m & 3, h = n >> 6, d = n & 63;
                    float* dst = (MODE == 0) ? g_q : (MODE == 1) ? g_k : g_v;
                    *(float2*)&dst[(((size_t)(b * H + h)) * TQ + t) * DH + d] = v;
                } else {
                    *(float2*)&Out[(size_t)m * CDIM + n] = v;
                }
            }
        }
}

// ---------------------------------------------------------------------------
// rowstats: per (bh, 128-row block): online softmax max/sum over all 2048 keys.
// S recomputed on tensor cores; outputs (m, 1/l) per row. No large writes.
// ---------------------------------------------------------------------------
constexpr int RS_SMEM = (128 * 68 + 64 * 136) * 4 + (512 + 128 + 128 + 128) * 4;

__global__ __launch_bounds__(256)
void rowstats_kernel(const unsigned char* __restrict__ mask)
{
    extern __shared__ char smraw[];
    unsigned* Qs   = (unsigned*)smraw;          // [m:128][k:64] stride 68
    unsigned* Ks   = Qs + 128 * 68;             // [k:64][n:128] stride 136
    float* red     = (float*)(Ks + 64 * 136);   // [4][128]
    float* m_run   = red + 512;
    float* l_run   = m_run + 128;
    float* mskf    = l_run + 128;

    const int tid = threadIdx.x, lane = tid & 31, wid = tid >> 5;
    const int gid = lane >> 2, tig = lane & 3;
    const int wm = wid >> 2, wn = wid & 3;
    const int m0 = blockIdx.x * 128, bh = blockIdx.y, b = bh >> 4;

#pragma unroll
    for (int i = 0; i < 8; i++) {
        int li = tid + i * 256;
        int r = li >> 4, c = li & 15;
        float4 a = *(const float4*)&g_q[((size_t)bh * TQ + m0 + r) * DH + c * 4];
        *(uint4*)&Qs[r * 68 + c * 4] =
            make_uint4(f2tf(a.x), f2tf(a.y), f2tf(a.z), f2tf(a.w));
    }
    if (tid < 128) { m_run[tid] = -INFINITY; l_run[tid] = 0.f; }
    __syncthreads();

    for (int nt = 0; nt < 16; nt++) {
        int n0 = nt * 128;
#pragma unroll
        for (int i = 0; i < 8; i++) {
            int li = tid + i * 256;
            int n = li >> 4, c = li & 15;
            float4 a = *(const float4*)&g_k[((size_t)bh * TK + n0 + n) * DH + c * 4];
            Ks[(c * 4 + 0) * 136 + n] = f2tf(a.x);
            Ks[(c * 4 + 1) * 136 + n] = f2tf(a.y);
            Ks[(c * 4 + 2) * 136 + n] = f2tf(a.z);
            Ks[(c * 4 + 3) * 136 + n] = f2tf(a.w);
        }
        if (tid < 128)
            mskf[tid] = mask[(size_t)b * TK + n0 + tid] ? -INFINITY : 0.f;
        __syncthreads();

        float acc[4][4][4] = {};
#pragma unroll
        for (int kk = 0; kk < 64; kk += 8) {
            unsigned af[4][4], bf[4][2];
#pragma unroll
            for (int mi = 0; mi < 4; mi++) {
                int rb = wm * 64 + mi * 16;
                af[mi][0] = Qs[(rb + gid)     * 68 + kk + tig];
                af[mi][1] = Qs[(rb + gid + 8) * 68 + kk + tig];
                af[mi][2] = Qs[(rb + gid)     * 68 + kk + tig + 4];
                af[mi][3] = Qs[(rb + gid + 8) * 68 + kk + tig + 4];
            }
#pragma unroll
            for (int ni = 0; ni < 4; ni++) {
                int cb = wn * 32 + ni * 8;
                bf[ni][0] = Ks[(kk + tig)     * 136 + cb + gid];
                bf[ni][1] = Ks[(kk + tig + 4) * 136 + cb + gid];
            }
#pragma unroll
            for (int mi = 0; mi < 4; mi++)
#pragma unroll
                for (int ni = 0; ni < 4; ni++) mma8(acc[mi][ni], af[mi], bf[ni]);
        }

        // apply mask additively
#pragma unroll
        for (int mi = 0; mi < 4; mi++)
#pragma unroll
            for (int ni = 0; ni < 4; ni++) {
                int cb = wn * 32 + ni * 8 + tig * 2;
                float mk0 = mskf[cb], mk1 = mskf[cb + 1];
                acc[mi][ni][0] += mk0; acc[mi][ni][1] += mk1;
                acc[mi][ni][2] += mk0; acc[mi][ni][3] += mk1;
            }

        // chunk row-max
#pragma unroll
        for (int mi = 0; mi < 4; mi++)
#pragma unroll
            for (int hl = 0; hl < 2; hl++) {
                float v = -INFINITY;
#pragma unroll
                for (int ni = 0; ni < 4; ni++) {
                    v = fmaxf(v, acc[mi][ni][hl * 2]);
                    v = fmaxf(v, acc[mi][ni][hl * 2 + 1]);
                }
                v = fmaxf(v, __shfl_xor_sync(~0u, v, 1));
                v = fmaxf(v, __shfl_xor_sync(~0u, v, 2));
                if (tig == 0) red[wn * 128 + wm * 64 + mi * 16 + gid + hl * 8] = v;
            }
        __syncthreads();
        if (tid < 128) {
            float cm = fmaxf(fmaxf(red[tid], red[128 + tid]),
                             fmaxf(red[256 + tid], red[384 + tid]));
            float mo = m_run[tid];
            float mn = fmaxf(mo, cm);
            float fac = (mo == mn) ? 1.f : __expf(mo - mn);
            l_run[tid] *= fac;
            m_run[tid] = mn;
        }
        __syncthreads();

        // chunk exp-sums
#pragma unroll
        for (int mi = 0; mi < 4; mi++)
#pragma unroll
            for (int hl = 0; hl < 2; hl++) {
                int row = wm * 64 + mi * 16 + gid + hl * 8;
                float mr = m_run[row];
                float s = 0.f;
#pragma unroll
                for (int ni = 0; ni < 4; ni++) {
                    s += __expf(acc[mi][ni][hl * 2]     - mr);
                    s += __expf(acc[mi][ni][hl * 2 + 1] - mr);
                }
                s += __shfl_xor_sync(~0u, s, 1);
                s += __shfl_xor_sync(~0u, s, 2);
                if (tig == 0) red[wn * 128 + row] = s;
            }
        __syncthreads();
        if (tid < 128)
            l_run[tid] += red[tid] + red[128 + tid] + red[256 + tid] + red[384 + tid];
        __syncthreads();
    }

    if (tid < 128) {
        float2 st; st.x = m_run[tid]; st.y = 1.f / l_run[tid];
        g_stats[(size_t)bh * TQ + m0 + tid] = st;
    }
}

// ---------------------------------------------------------------------------
// attn_av: recompute S, normalize with precomputed stats, write P to attn
// (coalesced via SMEM stage), and fused O += P @ V on tensor cores.
// ---------------------------------------------------------------------------
constexpr int AV_SMEM = (128 * 68 + 64 * 136 + 128 * 68) * 4
                      + (128 * 132 + 128 + 128 + 128) * 4;

__global__ __launch_bounds__(256)
void attn_av_kernel(const unsigned char* __restrict__ mask,
                    float* __restrict__ attn)
{
    extern __shared__ char smraw[];
    unsigned* Qs = (unsigned*)smraw;            // [128][68]
    unsigned* Ks = Qs + 128 * 68;               // [64][136]
    unsigned* Vs = Ks + 64 * 136;               // [128][68]
    float* Ps    = (float*)(Vs + 128 * 68);     // [128][132] fp32
    float* sm_m  = Ps + 128 * 132;
    float* sm_il = sm_m + 128;
    float* mskf  = sm_il + 128;

    const int tid = threadIdx.x, lane = tid & 31, wid = tid >> 5;
    const int gid = lane >> 2, tig = lane & 3;
    const int wm = wid >> 2, wn = wid & 3;
    const int m0 = blockIdx.x * 128, bh = blockIdx.y, b = bh >> 4;

#pragma unroll
    for (int i = 0; i < 8; i++) {
        int li = tid + i * 256;
        int r = li >> 4, c = li & 15;
        float4 a = *(const float4*)&g_q[((size_t)bh * TQ + m0 + r) * DH + c * 4];
        *(uint4*)&Qs[r * 68 + c * 4] =
            make_uint4(f2tf(a.x), f2tf(a.y), f2tf(a.z), f2tf(a.w));
    }
    if (tid < 128) {
        float2 st = g_stats[(size_t)bh * TQ + m0 + tid];
        sm_m[tid] = st.x; sm_il[tid] = st.y;
    }
    float acco[4][2][4] = {};
    __syncthreads();

    for (int nt = 0; nt < 16; nt++) {
        int n0 = nt * 128;
#pragma unroll
        for (int i = 0; i < 8; i++) {
            int li = tid + i * 256;
            int n = li >> 4, c = li & 15;
            float4 a = *(const float4*)&g_k[((size_t)bh * TK + n0 + n) * DH + c * 4];
            Ks[(c * 4 + 0) * 136 + n] = f2tf(a.x);
            Ks[(c * 4 + 1) * 136 + n] = f2tf(a.y);
            Ks[(c * 4 + 2) * 136 + n] = f2tf(a.z);
            Ks[(c * 4 + 3) * 136 + n] = f2tf(a.w);
            float4 vv = *(const float4*)&g_v[((size_t)bh * TK + n0 + n) * DH + c * 4];
            *(uint4*)&Vs[n * 68 + c * 4] =
                make_uint4(f2tf(vv.x), f2tf(vv.y), f2tf(vv.z), f2tf(vv.w));
        }
        if (tid < 128)
            mskf[tid] = mask[(size_t)b * TK + n0 + tid] ? -INFINITY : 0.f;
        __syncthreads();

        float acc[4][4][4] = {};
#pragma unroll
        for (int kk = 0; kk < 64; kk += 8) {
            unsigned af[4][4], bf[4][2];
#pragma unroll
            for (int mi = 0; mi < 4; mi++) {
                int rb = wm * 64 + mi * 16;
                af[mi][0] = Qs[(rb + gid)     * 68 + kk + tig];
                af[mi][1] = Qs[(rb + gid + 8) * 68 + kk + tig];
                af[mi][2] = Qs[(rb + gid)     * 68 + kk + tig + 4];
                af[mi][3] = Qs[(rb + gid + 8) * 68 + kk + tig + 4];
            }
#pragma unroll
            for (int ni = 0; ni < 4; ni++) {
                int cb = wn * 32 + ni * 8;
                bf[ni][0] = Ks[(kk + tig)     * 136 + cb + gid];
                bf[ni][1] = Ks[(kk + tig + 4) * 136 + cb + gid];
            }
#pragma unroll
            for (int mi = 0; mi < 4; mi++)
#pragma unroll
                for (int ni = 0; ni < 4; ni++) mma8(acc[mi][ni], af[mi], bf[ni]);
        }

        // p = exp(s + mask - m) / l ; stage into Ps
#pragma unroll
        for (int mi = 0; mi < 4; mi++)
#pragma unroll
            for (int hl = 0; hl < 2; hl++) {
                int row = wm * 64 + mi * 16 + gid + hl * 8;
                float mr = sm_m[row], il = sm_il[row];
#pragma unroll
                for (int ni = 0; ni < 4; ni++) {
                    int cb = wn * 32 + ni * 8 + tig * 2;
                    float p0 = __expf(acc[mi][ni][hl * 2]     + mskf[cb]     - mr) * il;
                    float p1 = __expf(acc[mi][ni][hl * 2 + 1] + mskf[cb + 1] - mr) * il;
                    *(float2*)&Ps[row * 132 + cb] = make_float2(p0, p1);
                }
            }
        __syncthreads();

        // coalesced write of normalized attention tile (the ONLY attn traffic)
#pragma unroll
        for (int i = 0; i < 16; i++) {
            int li = tid + i * 256;
            int r = li >> 5, c = li & 31;
            float4 v = *(float4*)&Ps[r * 132 + c * 4];
            *(float4*)&attn[((size_t)bh * TQ + m0 + r) * TK + n0 + c * 4] = v;
        }

        // fused O += P @ V   (k = 128)
#pragma unroll
        for (int kk = 0; kk < 128; kk += 8) {
            unsigned af[4][4], bf[2][2];
#pragma unroll
            for (int mi = 0; mi < 4; mi++) {
                int rb = wm * 64 + mi * 16;
                af[mi][0] = f2tf(Ps[(rb + gid)     * 132 + kk + tig]);
                af[mi][1] = f2tf(Ps[(rb + gid + 8) * 132 + kk + tig]);
                af[mi][2] = f2tf(Ps[(rb + gid)     * 132 + kk + tig + 4]);
                af[mi][3] = f2tf(Ps[(rb + gid + 8) * 132 + kk + tig + 4]);
            }
#pragma unroll
            for (int ni = 0; ni < 2; ni++) {
                int cb = wn * 16 + ni * 8;
                bf[ni][0] = Vs[(kk + tig)     * 68 + cb + gid];
                bf[ni][1] = Vs[(kk + tig + 4) * 68 + cb + gid];
            }
#pragma unroll
            for (int mi = 0; mi < 4; mi++)
#pragma unroll
                for (int ni = 0; ni < 2; ni++) mma8(acco[mi][ni], af[mi], bf[ni]);
        }
        __syncthreads();
    }

    // write O to g_x [bh, t, d]
#pragma unroll
    for (int mi = 0; mi < 4; mi++)
#pragma unroll
        for (int hl = 0; hl < 2; hl++) {
            int row = m0 + wm * 64 + mi * 16 + gid + hl * 8;
#pragma unroll
            for (int ni = 0; ni < 2; ni++) {
                int c = wn * 16 + ni * 8 + tig * 2;
                *(float2*)&g_x[((size_t)bh * TQ + row) * DH + c] =
                    make_float2(acco[mi][ni][hl * 2], acco[mi][ni][hl * 2 + 1]);
            }
        }
}

// ---------------------------------------------------------------------------
extern "C" void kernel_launch(void* const* d_in, const int* in_sizes, int n_in,
                              void* d_out, int out_size)
{
    const float* query = (const float*)d_in[0];
    const float* key   = (const float*)d_in[1];
    const float* value = (const float*)d_in[2];
    const unsigned char* mask = (const unsigned char*)d_in[3];
    const float* Wq = (const float*)d_in[4];
    const float* bq = (const float*)d_in[5];
    const float* Wk = (const float*)d_in[6];
    const float* bk = (const float*)d_in[7];
    const float* Wv = (const float*)d_in[8];
    const float* bv = (const float*)d_in[9];
    const float* Wo = (const float*)d_in[10];
    const float* bo = (const float*)d_in[11];

    float* out_x = (float*)d_out;                       // [2048,4,1024]
    float* attn  = out_x + (size_t)TQ * BSZ * CDIM;     // [64,2048,2048]

    cudaFuncSetAttribute(rowstats_kernel,
                         cudaFuncAttributeMaxDynamicSharedMemorySize, RS_SMEM);
    cudaFuncSetAttribute(attn_av_kernel,
                         cudaFuncAttributeMaxDynamicSharedMemorySize, AV_SMEM);

    const float scale = 0.125f;   // 1/sqrt(64)
    dim3 blk(256);

    proj_kernel<0><<<dim3(8, 64), blk>>>(query, Wq, bq, nullptr, scale);
    proj_kernel<1><<<dim3(8, 64), blk>>>(key,   Wk, bk, nullptr, 1.f);
    proj_kernel<2><<<dim3(8, 64), blk>>>(value, Wv, bv, nullptr, 1.f);
    rowstats_kernel<<<dim3(16, 64), blk, RS_SMEM>>>(mask);
    attn_av_kernel<<<dim3(16, 64), blk, AV_SMEM>>>(mask, attn);
    proj_kernel<3><<<dim3(8, 64), blk>>>(nullptr, Wo, bo, out_x, 1.f);
}

// round 4
// speedup vs baseline: 1.6334x; 1.0933x over previous
#include <cuda_runtime.h>
#include <math.h>

// ---------------------------------------------------------------------------
// Round 4: one-pass fused attention (no rowstats), tf32 mma.sync everywhere.
//   proj(q,k,v) -> attn_fused (S, exp unnormalized -> attn + rowsum + P@V,
//   O normalized in-kernel) -> rescale(attn *= 1/l) -> out projection.
// ---------------------------------------------------------------------------

constexpr int TQ  = 2048;
constexpr int TK  = 2048;
constexpr int BSZ = 4;
constexpr int CDIM = 1024;
constexpr int H   = 16;
constexpr int DH  = 64;
constexpr int BH  = BSZ * H;   // 64

__device__ float g_q[(size_t)BH * TQ * DH];
__device__ float g_k[(size_t)BH * TK * DH];
__device__ float g_v[(size_t)BH * TK * DH];
__device__ float g_x[(size_t)BH * TQ * DH];
__device__ float g_linv[(size_t)BH * TQ];

__device__ __forceinline__ unsigned f2tf(float x) {
    unsigned r; asm("cvt.rna.tf32.f32 %0, %1;" : "=r"(r) : "f"(x)); return r;
}
__device__ __forceinline__ void mma8(float* d, const unsigned* a, const unsigned* b) {
    asm volatile(
        "mma.sync.aligned.m16n8k8.row.col.f32.tf32.tf32.f32 "
        "{%0,%1,%2,%3},{%4,%5,%6,%7},{%8,%9},{%0,%1,%2,%3};"
        : "+f"(d[0]), "+f"(d[1]), "+f"(d[2]), "+f"(d[3])
        : "r"(a[0]), "r"(a[1]), "r"(a[2]), "r"(a[3]), "r"(b[0]), "r"(b[1]));
}

// ---------------------------------------------------------------------------
// Projection GEMM (unchanged from round 3): C = A @ W (+bias)*scale
// ---------------------------------------------------------------------------
template<int MODE>
__global__ __launch_bounds__(256)
void proj_kernel(const float* __restrict__ A, const float* __restrict__ W,
                 const float* __restrict__ bias, float* __restrict__ Out,
                 float scale)
{
    __shared__ unsigned As[128 * 36];
    __shared__ unsigned Bs[32 * 136];

    const int tid = threadIdx.x, lane = tid & 31, wid = tid >> 5;
    const int gid = lane >> 2, tig = lane & 3;
    const int wm = wid >> 2, wn = wid & 3;
    const int m0 = blockIdx.y * 128, n0 = blockIdx.x * 128;

    float acc[4][4][4] = {};

    for (int k0 = 0; k0 < CDIM; k0 += 32) {
#pragma unroll
        for (int i = 0; i < 4; i++) {
            int li = tid + i * 256;
            int r = li >> 3, c = li & 7;
            float4 a;
            if (MODE < 3) {
                a = *(const float4*)&A[(size_t)(m0 + r) * CDIM + k0 + c * 4];
            } else {
                int m = m0 + r, t = m >> 2, b = m & 3;
                int k = k0 + c * 4, h = k >> 6, d = k & 63;
                a = *(const float4*)&g_x[(((size_t)(b * H + h)) * TQ + t) * DH + d];
            }
            *(uint4*)&As[r * 36 + c * 4] =
                make_uint4(f2tf(a.x), f2tf(a.y), f2tf(a.z), f2tf(a.w));
        }
#pragma unroll
        for (int i = 0; i < 4; i++) {
            int li = tid + i * 256;
            int r = li >> 5, c = li & 31;
            float4 b = *(const float4*)&W[(size_t)(k0 + r) * CDIM + n0 + c * 4];
            *(uint4*)&Bs[r * 136 + c * 4] =
                make_uint4(f2tf(b.x), f2tf(b.y), f2tf(b.z), f2tf(b.w));
        }
        __syncthreads();

#pragma unroll
        for (int kk = 0; kk < 32; kk += 8) {
            unsigned af[4][4], bf[4][2];
#pragma unroll
            for (int mi = 0; mi < 4; mi++) {
                int rb = wm * 64 + mi * 16;
                af[mi][0] = As[(rb + gid)     * 36 + kk + tig];
                af[mi][1] = As[(rb + gid + 8) * 36 + kk + tig];
                af[mi][2] = As[(rb + gid)     * 36 + kk + tig + 4];
                af[mi][3] = As[(rb + gid + 8) * 36 + kk + tig + 4];
            }
#pragma unroll
            for (int ni = 0; ni < 4; ni++) {
                int cb = wn * 32 + ni * 8;
                bf[ni][0] = Bs[(kk + tig)     * 136 + cb + gid];
                bf[ni][1] = Bs[(kk + tig + 4) * 136 + cb + gid];
            }
#pragma unroll
            for (int mi = 0; mi < 4; mi++)
#pragma unroll
                for (int ni = 0; ni < 4; ni++) mma8(acc[mi][ni], af[mi], bf[ni]);
        }
        __syncthreads();
    }

#pragma unroll
    for (int mi = 0; mi < 4; mi++)
#pragma unroll
        for (int hl = 0; hl < 2; hl++) {
            int m = m0 + wm * 64 + mi * 16 + gid + hl * 8;
#pragma unroll
            for (int ni = 0; ni < 4; ni++) {
                int n = n0 + wn * 32 + ni * 8 + tig * 2;
                float2 v;
                v.x = (acc[mi][ni][hl * 2 + 0] + bias[n + 0]) * scale;
                v.y = (acc[mi][ni][hl * 2 + 1] + bias[n + 1]) * scale;
                if (MODE < 3) {
                    int t = m >> 2, b = m & 3, h = n >> 6, d = n & 63;
                    float* dst = (MODE == 0) ? g_q : (MODE == 1) ? g_k : g_v;
                    *(float2*)&dst[(((size_t)(b * H + h)) * TQ + t) * DH + d] = v;
                } else {
                    *(float2*)&Out[(size_t)m * CDIM + n] = v;
                }
            }
        }
}

// ---------------------------------------------------------------------------
// attn_fused: per (m-block 128, bh): Q loaded once (perm layout). For each of
// 16 key tiles: S = QK^T (mma), E = exp(S+mask) written UNNORMALIZED directly
// to attn from fragments, rowsum accumulated, E staged as tf32 (perm layout),
// O += E@V (mma). Epilogue: O *= 1/l, 1/l -> g_linv.
// smem u32 offsets:
//   Qs 0..8704 [128][68] perm-col, Ks 8704..17408 [64][136],
//   Vs 17408..26112 [128][68], Ps 26112..43008 [128][132] tf32 perm-col,
//   red 43008..43520, sm_inv 43520..43648, mskf 43648..43776
// ---------------------------------------------------------------------------
constexpr int AT_SMEM = 43776 * 4;

__global__ __launch_bounds__(256, 1)
void attn_fused_kernel(const unsigned char* __restrict__ mask,
                       float* __restrict__ attn)
{
    extern __shared__ unsigned smem_u[];
    unsigned* Qs = smem_u;
    unsigned* Ks = smem_u + 8704;
    unsigned* Vs = smem_u + 17408;
    unsigned* Ps = smem_u + 26112;
    float* red    = (float*)(smem_u + 43008);
    float* sm_inv = (float*)(smem_u + 43520);
    float* mskf   = (float*)(smem_u + 43648);

    const int tid = threadIdx.x, lane = tid & 31, wid = tid >> 5;
    const int gid = lane >> 2, tig = lane & 3;
    const int wm = wid >> 2, wn = wid & 3;
    const int m0 = blockIdx.x * 128, bh = blockIdx.y, b = bh >> 4;

    // ---- Q -> smem, permuted columns: k -> (k&~7) + (k&3)*2 + ((k>>2)&1)
#pragma unroll
    for (int i = 0; i < 8; i++) {
        int li = tid + i * 256;
        int r = li >> 4, c = li & 15;
        float4 a = *(const float4*)&g_q[((size_t)bh * TQ + m0 + r) * DH + c * 4];
        unsigned* q = &Qs[r * 68 + (c >> 1) * 8 + (c & 1)];
        q[0] = f2tf(a.x); q[2] = f2tf(a.y); q[4] = f2tf(a.z); q[6] = f2tf(a.w);
    }

    // ---- prefetch first K/V tile into registers
    float4 kreg[8], vreg[8];
#pragma unroll
    for (int i = 0; i < 8; i++) {
        int li = tid + i * 256;
        int n = li >> 4, c = li & 15;
        kreg[i] = *(const float4*)&g_k[((size_t)bh * TK + n) * DH + c * 4];
        vreg[i] = *(const float4*)&g_v[((size_t)bh * TK + n) * DH + c * 4];
    }

    float acco[4][2][4] = {};
    float lsum[4][2] = {};
    const int perm0 = ((2 * tig) & 3) * 2 + (tig >> 1);   // store pos of col 2tig

    for (int nt = 0; nt < 16; nt++) {
        const int n0 = nt * 128;
        __syncthreads();   // prior PV done reading Ks/Vs/Ps

        // ---- stage K (transposed [d][n]) and V ([n][d]) from registers
#pragma unroll
        for (int i = 0; i < 8; i++) {
            int li = tid + i * 256;
            int n = li >> 4, c = li & 15;
            Ks[(c * 4 + 0) * 136 + n] = f2tf(kreg[i].x);
            Ks[(c * 4 + 1) * 136 + n] = f2tf(kreg[i].y);
            Ks[(c * 4 + 2) * 136 + n] = f2tf(kreg[i].z);
            Ks[(c * 4 + 3) * 136 + n] = f2tf(kreg[i].w);
            *(uint4*)&Vs[n * 68 + c * 4] =
                make_uint4(f2tf(vreg[i].x), f2tf(vreg[i].y),
                           f2tf(vreg[i].z), f2tf(vreg[i].w));
        }
        if (tid < 128)
            mskf[tid] = mask[(size_t)b * TK + n0 + tid] ? -INFINITY : 0.f;
        __syncthreads();

        // ---- prefetch next tile (latency hidden behind S-mma)
        if (nt < 15) {
#pragma unroll
            for (int i = 0; i < 8; i++) {
                int li = tid + i * 256;
                int n = li >> 4, c = li & 15;
                kreg[i] = *(const float4*)&g_k[((size_t)bh * TK + n0 + 128 + n) * DH + c * 4];
                vreg[i] = *(const float4*)&g_v[((size_t)bh * TK + n0 + 128 + n) * DH + c * 4];
            }
        }

        // ---- S = Q @ K^T
        float acc[4][4][4] = {};
#pragma unroll
        for (int kk = 0; kk < 64; kk += 8) {
            unsigned af[4][4], bf[4][2];
#pragma unroll
            for (int mi = 0; mi < 4; mi++) {
                int rb = wm * 64 + mi * 16;
                uint2 lo = *(const uint2*)&Qs[(rb + gid)     * 68 + kk + tig * 2];
                uint2 hi = *(const uint2*)&Qs[(rb + gid + 8) * 68 + kk + tig * 2];
                af[mi][0] = lo.x; af[mi][1] = hi.x; af[mi][2] = lo.y; af[mi][3] = hi.y;
            }
#pragma unroll
            for (int ni = 0; ni < 4; ni++) {
                int cb = wn * 32 + ni * 8;
                bf[ni][0] = Ks[(kk + tig)     * 136 + cb + gid];
                bf[ni][1] = Ks[(kk + tig + 4) * 136 + cb + gid];
            }
#pragma unroll
            for (int mi = 0; mi < 4; mi++)
#pragma unroll
                for (int ni = 0; ni < 4; ni++) mma8(acc[mi][ni], af[mi], bf[ni]);
        }

        // ---- mask regs (same cols for every row this thread owns)
        float mk[4][2];
#pragma unroll
        for (int ni = 0; ni < 4; ni++) {
            float2 mm = *(const float2*)&mskf[wn * 32 + ni * 8 + 2 * tig];
            mk[ni][0] = mm.x; mk[ni][1] = mm.y;
        }

        // ---- E = exp(S+mask): direct global write, rowsum, tf32 stage
#pragma unroll
        for (int mi = 0; mi < 4; mi++) {
            int rb = wm * 64 + mi * 16;
#pragma unroll
            for (int hl = 0; hl < 2; hl++) {
                int row = rb + gid + hl * 8;
                float* arow = attn + ((size_t)bh * TQ + m0 + row) * TK + n0;
                float ls = 0.f;
#pragma unroll
                for (int ni = 0; ni < 4; ni++) {
                    int cb = wn * 32 + ni * 8;
                    float p0 = __expf(acc[mi][ni][hl * 2]     + mk[ni][0]);
                    float p1 = __expf(acc[mi][ni][hl * 2 + 1] + mk[ni][1]);
                    *(float2*)&arow[cb + 2 * tig] = make_float2(p0, p1);
                    unsigned* pp = &Ps[row * 132 + cb + perm0];
                    pp[0] = f2tf(p0); pp[2] = f2tf(p1);
                    ls += p0 + p1;
                }
                lsum[mi][hl] += ls;
            }
        }
        __syncthreads();

        // ---- O += E @ V  (k over 128 keys)
#pragma unroll
        for (int kk = 0; kk < 128; kk += 8) {
            unsigned af[4][4], bf[2][2];
#pragma unroll
            for (int mi = 0; mi < 4; mi++) {
                int rb = wm * 64 + mi * 16;
                uint2 lo = *(const uint2*)&Ps[(rb + gid)     * 132 + kk + tig * 2];
                uint2 hi = *(const uint2*)&Ps[(rb + gid + 8) * 132 + kk + tig * 2];
                af[mi][0] = lo.x; af[mi][1] = hi.x; af[mi][2] = lo.y; af[mi][3] = hi.y;
            }
#pragma unroll
            for (int ni = 0; ni < 2; ni++) {
                int cb = wn * 16 + ni * 8;
                bf[ni][0] = Vs[(kk + tig)     * 68 + cb + gid];
                bf[ni][1] = Vs[(kk + tig + 4) * 68 + cb + gid];
            }
#pragma unroll
            for (int mi = 0; mi < 4; mi++)
#pragma unroll
                for (int ni = 0; ni < 2; ni++) mma8(acco[mi][ni], af[mi], bf[ni]);
        }
    }

    // ---- reduce rowsums: tig lanes -> wn warps -> 1/l
    __syncthreads();
#pragma unroll
    for (int mi = 0; mi < 4; mi++)
#pragma unroll
        for (int hl = 0; hl < 2; hl++) {
            float v = lsum[mi][hl];
            v += __shfl_xor_sync(~0u, v, 1);
            v += __shfl_xor_sync(~0u, v, 2);
            if (tig == 0) red[wn * 128 + wm * 64 + mi * 16 + gid + hl * 8] = v;
        }
    __syncthreads();
    if (tid < 128) {
        float l = red[tid] + red[128 + tid] + red[256 + tid] + red[384 + tid];
        float inv = 1.f / l;
        sm_inv[tid] = inv;
        g_linv[(size_t)bh * TQ + m0 + tid] = inv;
    }
    __syncthreads();

    // ---- O normalize + write g_x [bh, t, d]
#pragma unroll
    for (int mi = 0; mi < 4; mi++)
#pragma unroll
        for (int hl = 0; hl < 2; hl++) {
            int row = wm * 64 + mi * 16 + gid + hl * 8;
            float inv = sm_inv[row];
#pragma unroll
            for (int ni = 0; ni < 2; ni++) {
                int c = wn * 16 + ni * 8 + tig * 2;
                *(float2*)&g_x[((size_t)bh * TQ + m0 + row) * DH + c] =
                    make_float2(acco[mi][ni][hl * 2] * inv,
                                acco[mi][ni][hl * 2 + 1] * inv);
            }
        }
}

// ---------------------------------------------------------------------------
// rescale: attn[row, :] *= g_linv[row]   (one block per row)
// ---------------------------------------------------------------------------
__global__ __launch_bounds__(256)
void rescale_kernel(float* __restrict__ attn)
{
    const size_t row = blockIdx.x;
    const float inv = g_linv[row];
    float4* p = (float4*)(attn + row * (size_t)TK);
    const int tid = threadIdx.x;
#pragma unroll
    for (int i = 0; i < 2; i++) {
        float4 v = p[tid + i * 256];
        v.x *= inv; v.y *= inv; v.z *= inv; v.w *= inv;
        p[tid + i * 256] = v;
    }
}

// ---------------------------------------------------------------------------
extern "C" void kernel_launch(void* const* d_in, const int* in_sizes, int n_in,
                              void* d_out, int out_size)
{
    const float* query = (const float*)d_in[0];
    const float* key   = (const float*)d_in[1];
    const float* value = (const float*)d_in[2];
    const unsigned char* mask = (const unsigned char*)d_in[3];
    const float* Wq = (const float*)d_in[4];
    const float* bq = (const float*)d_in[5];
    const float* Wk = (const float*)d_in[6];
    const float* bk = (const float*)d_in[7];
    const float* Wv = (const float*)d_in[8];
    const float* bv = (const float*)d_in[9];
    const float* Wo = (const float*)d_in[10];
    const float* bo = (const float*)d_in[11];

    float* out_x = (float*)d_out;                       // [2048,4,1024]
    float* attn  = out_x + (size_t)TQ * BSZ * CDIM;     // [64,2048,2048]

    cudaFuncSetAttribute(attn_fused_kernel,
                         cudaFuncAttributeMaxDynamicSharedMemorySize, AT_SMEM);

    const float scale = 0.125f;   // 1/sqrt(64)
    dim3 blk(256);

    proj_kernel<0><<<dim3(8, 64), blk>>>(query, Wq, bq, nullptr, scale);
    proj_kernel<1><<<dim3(8, 64), blk>>>(key,   Wk, bk, nullptr, 1.f);
    proj_kernel<2><<<dim3(8, 64), blk>>>(value, Wv, bv, nullptr, 1.f);
    attn_fused_kernel<<<dim3(16, 64), blk, AT_SMEM>>>(mask, attn);
    rescale_kernel<<<dim3(BH * TQ), blk>>>(attn);
    proj_kernel<3><<<dim3(8, 64), blk>>>(nullptr, Wo, bo, out_x, 1.f);
}

// round 5
// speedup vs baseline: 1.8931x; 1.1590x over previous
#include <cuda_runtime.h>
#include <math.h>

// ---------------------------------------------------------------------------
// Round 5: cp.async double-buffered fused attention (no register spills),
// merged QKV projection launch. tf32 mma.sync, fp32 accumulation.
// ---------------------------------------------------------------------------

constexpr int TQ  = 2048;
constexpr int TK  = 2048;
constexpr int BSZ = 4;
constexpr int CDIM = 1024;
constexpr int H   = 16;
constexpr int DH  = 64;
constexpr int BH  = BSZ * H;   // 64

__device__ float g_q[(size_t)BH * TQ * DH];
__device__ float g_k[(size_t)BH * TK * DH];
__device__ float g_v[(size_t)BH * TK * DH];
__device__ float g_x[(size_t)BH * TQ * DH];
__device__ float g_linv[(size_t)BH * TQ];

__device__ __forceinline__ unsigned f2tf(float x) {
    unsigned r; asm("cvt.rna.tf32.f32 %0, %1;" : "=r"(r) : "f"(x)); return r;
}
__device__ __forceinline__ void mma8(float* d, const unsigned* a, const unsigned* b) {
    asm volatile(
        "mma.sync.aligned.m16n8k8.row.col.f32.tf32.tf32.f32 "
        "{%0,%1,%2,%3},{%4,%5,%6,%7},{%8,%9},{%0,%1,%2,%3};"
        : "+f"(d[0]), "+f"(d[1]), "+f"(d[2]), "+f"(d[3])
        : "r"(a[0]), "r"(a[1]), "r"(a[2]), "r"(a[3]), "r"(b[0]), "r"(b[1]));
}
__device__ __forceinline__ unsigned sptr(const void* p) {
    return (unsigned)__cvta_generic_to_shared(p);
}
#define CP16(dst_u32, src_ptr) \
    asm volatile("cp.async.cg.shared.global [%0], [%1], 16;" :: "r"(dst_u32), "l"(src_ptr))
#define CP_COMMIT() asm volatile("cp.async.commit_group;")

// ---------------------------------------------------------------------------
// Merged QKV projection: blockIdx.z selects (A, W, bias, dst, scale).
// Block tile 128x128, k-step 32; warp grid 2x4, warp tile 64x32.
// ---------------------------------------------------------------------------
__global__ __launch_bounds__(256)
void qkv_proj_kernel(const float* __restrict__ Aq, const float* __restrict__ Ak,
                     const float* __restrict__ Av,
                     const float* __restrict__ Wq, const float* __restrict__ Wk,
                     const float* __restrict__ Wv,
                     const float* __restrict__ bq, const float* __restrict__ bk,
                     const float* __restrict__ bv)
{
    __shared__ unsigned As[128 * 36];
    __shared__ unsigned Bs[32 * 136];

    const int z = blockIdx.z;
    const float* A    = (z == 0) ? Aq : (z == 1) ? Ak : Av;
    const float* W    = (z == 0) ? Wq : (z == 1) ? Wk : Wv;
    const float* bias = (z == 0) ? bq : (z == 1) ? bk : bv;
    float* dst        = (z == 0) ? g_q : (z == 1) ? g_k : g_v;
    const float scale = (z == 0) ? 0.125f : 1.f;

    const int tid = threadIdx.x, lane = tid & 31, wid = tid >> 5;
    const int gid = lane >> 2, tig = lane & 3;
    const int wm = wid >> 2, wn = wid & 3;
    const int m0 = blockIdx.y * 128, n0 = blockIdx.x * 128;

    float acc[4][4][4] = {};

    for (int k0 = 0; k0 < CDIM; k0 += 32) {
#pragma unroll
        for (int i = 0; i < 4; i++) {
            int li = tid + i * 256;
            int r = li >> 3, c = li & 7;
            float4 a = *(const float4*)&A[(size_t)(m0 + r) * CDIM + k0 + c * 4];
            *(uint4*)&As[r * 36 + c * 4] =
                make_uint4(f2tf(a.x), f2tf(a.y), f2tf(a.z), f2tf(a.w));
        }
#pragma unroll
        for (int i = 0; i < 4; i++) {
            int li = tid + i * 256;
            int r = li >> 5, c = li & 31;
            float4 b = *(const float4*)&W[(size_t)(k0 + r) * CDIM + n0 + c * 4];
            *(uint4*)&Bs[r * 136 + c * 4] =
                make_uint4(f2tf(b.x), f2tf(b.y), f2tf(b.z), f2tf(b.w));
        }
        __syncthreads();

#pragma unroll
        for (int kk = 0; kk < 32; kk += 8) {
            unsigned af[4][4], bf[4][2];
#pragma unroll
            for (int mi = 0; mi < 4; mi++) {
                int rb = wm * 64 + mi * 16;
                af[mi][0] = As[(rb + gid)     * 36 + kk + tig];
                af[mi][1] = As[(rb + gid + 8) * 36 + kk + tig];
                af[mi][2] = As[(rb + gid)     * 36 + kk + tig + 4];
                af[mi][3] = As[(rb + gid + 8) * 36 + kk + tig + 4];
            }
#pragma unroll
            for (int ni = 0; ni < 4; ni++) {
                int cb = wn * 32 + ni * 8;
                bf[ni][0] = Bs[(kk + tig)     * 136 + cb + gid];
                bf[ni][1] = Bs[(kk + tig + 4) * 136 + cb + gid];
            }
#pragma unroll
            for (int mi = 0; mi < 4; mi++)
#pragma unroll
                for (int ni = 0; ni < 4; ni++) mma8(acc[mi][ni], af[mi], bf[ni]);
        }
        __syncthreads();
    }

#pragma unroll
    for (int mi = 0; mi < 4; mi++)
#pragma unroll
        for (int hl = 0; hl < 2; hl++) {
            int m = m0 + wm * 64 + mi * 16 + gid + hl * 8;
#pragma unroll
            for (int ni = 0; ni < 4; ni++) {
                int n = n0 + wn * 32 + ni * 8 + tig * 2;
                float2 v;
                v.x = (acc[mi][ni][hl * 2 + 0] + bias[n + 0]) * scale;
                v.y = (acc[mi][ni][hl * 2 + 1] + bias[n + 1]) * scale;
                int t = m >> 2, b = m & 3, h = n >> 6, d = n & 63;
                *(float2*)&dst[(((size_t)(b * H + h)) * TQ + t) * DH + d] = v;
            }
        }
}

// ---------------------------------------------------------------------------
// Output projection (gathers A from g_x).
// ---------------------------------------------------------------------------
__global__ __launch_bounds__(256)
void out_proj_kernel(const float* __restrict__ W, const float* __restrict__ bias,
                     float* __restrict__ Out)
{
    __shared__ unsigned As[128 * 36];
    __shared__ unsigned Bs[32 * 136];

    const int tid = threadIdx.x, lane = tid & 31, wid = tid >> 5;
    const int gid = lane >> 2, tig = lane & 3;
    const int wm = wid >> 2, wn = wid & 3;
    const int m0 = blockIdx.y * 128, n0 = blockIdx.x * 128;

    float acc[4][4][4] = {};

    for (int k0 = 0; k0 < CDIM; k0 += 32) {
#pragma unroll
        for (int i = 0; i < 4; i++) {
            int li = tid + i * 256;
            int r = li >> 3, c = li & 7;
            int m = m0 + r, t = m >> 2, b = m & 3;
            int k = k0 + c * 4, h = k >> 6, d = k & 63;
            float4 a = *(const float4*)&g_x[(((size_t)(b * H + h)) * TQ + t) * DH + d];
            *(uint4*)&As[r * 36 + c * 4] =
                make_uint4(f2tf(a.x), f2tf(a.y), f2tf(a.z), f2tf(a.w));
        }
#pragma unroll
        for (int i = 0; i < 4; i++) {
            int li = tid + i * 256;
            int r = li >> 5, c = li & 31;
            float4 b = *(const float4*)&W[(size_t)(k0 + r) * CDIM + n0 + c * 4];
            *(uint4*)&Bs[r * 136 + c * 4] =
                make_uint4(f2tf(b.x), f2tf(b.y), f2tf(b.z), f2tf(b.w));
        }
        __syncthreads();

#pragma unroll
        for (int kk = 0; kk < 32; kk += 8) {
            unsigned af[4][4], bf[4][2];
#pragma unroll
            for (int mi = 0; mi < 4; mi++) {
                int rb = wm * 64 + mi * 16;
                af[mi][0] = As[(rb + gid)     * 36 + kk + tig];
                af[mi][1] = As[(rb + gid + 8) * 36 + kk + tig];
                af[mi][2] = As[(rb + gid)     * 36 + kk + tig + 4];
                af[mi][3] = As[(rb + gid + 8) * 36 + kk + tig + 4];
            }
#pragma unroll
            for (int ni = 0; ni < 4; ni++) {
                int cb = wn * 32 + ni * 8;
                bf[ni][0] = Bs[(kk + tig)     * 136 + cb + gid];
                bf[ni][1] = Bs[(kk + tig + 4) * 136 + cb + gid];
            }
#pragma unroll
            for (int mi = 0; mi < 4; mi++)
#pragma unroll
                for (int ni = 0; ni < 4; ni++) mma8(acc[mi][ni], af[mi], bf[ni]);
        }
        __syncthreads();
    }

#pragma unroll
    for (int mi = 0; mi < 4; mi++)
#pragma unroll
        for (int hl = 0; hl < 2; hl++) {
            int m = m0 + wm * 64 + mi * 16 + gid + hl * 8;
#pragma unroll
            for (int ni = 0; ni < 4; ni++) {
                int n = n0 + wn * 32 + ni * 8 + tig * 2;
                float2 v;
                v.x = acc[mi][ni][hl * 2 + 0] + bias[n + 0];
                v.y = acc[mi][ni][hl * 2 + 1] + bias[n + 1];
                *(float2*)&Out[(size_t)m * CDIM + n] = v;
            }
        }
}

// ---------------------------------------------------------------------------
// attn_fused: per (m-block 128, bh). Q resident tf32-perm in smem. Per key
// tile: S = QK^T (K raw fp32 [n][d] via cp.async, cvt at frag load),
// E = exp(S+mask) -> attn (unnormalized) + rowsum + Ps (tf32 perm),
// O += E@V (V raw fp32 [n][d] via cp.async). Epilogue: O *= 1/l -> g_x, g_linv.
// smem u32 map: Qs 0..8704 | Ks[2] 8704..26112 | Vs 26112..34816 |
//   Ps 34816..51712 | mskAll 51712..53760 | red 53760..54272 | sm_inv ..54400
// ---------------------------------------------------------------------------
constexpr int AT_SMEM = 54400 * 4;   // 217.6 KB

__global__ __launch_bounds__(256, 1)
void attn_fused_kernel(const unsigned char* __restrict__ mask,
                       float* __restrict__ attn)
{
    extern __shared__ unsigned smem_u[];
    unsigned* Qs  = smem_u;
    unsigned* Ks0 = smem_u + 8704;                 // raw fp32 bits, [n:128][d] s68
    unsigned* Ks1 = smem_u + 8704 + 8704;
    float*    Vsf = (float*)(smem_u + 26112);      // raw fp32, [n:128][d] s68
    unsigned* Ps  = smem_u + 34816;                // [128][132] tf32 perm
    float* mskAll = (float*)(smem_u + 51712);      // [2048]
    float* red    = (float*)(smem_u + 53760);
    float* sm_inv = (float*)(smem_u + 54272);

    const int tid = threadIdx.x, lane = tid & 31, wid = tid >> 5;
    const int gid = lane >> 2, tig = lane & 3;
    const int wm = wid >> 2, wn = wid & 3;
    const int m0 = blockIdx.x * 128, bh = blockIdx.y, b = bh >> 4;

    const float* kbase = g_k + (size_t)bh * TK * DH;
    const float* vbase = g_v + (size_t)bh * TK * DH;

    // ---- Q -> smem tf32, permuted cols: k -> (k&~7) + (k&3)*2 + ((k>>2)&1)
#pragma unroll
    for (int i = 0; i < 8; i++) {
        int li = tid + i * 256;
        int r = li >> 4, c = li & 15;
        float4 a = *(const float4*)&g_q[((size_t)bh * TQ + m0 + r) * DH + c * 4];
        unsigned* q = &Qs[r * 68 + (c >> 1) * 8 + (c & 1)];
        q[0] = f2tf(a.x); q[2] = f2tf(a.y); q[4] = f2tf(a.z); q[6] = f2tf(a.w);
    }
    // ---- full mask row -> smem floats
#pragma unroll
    for (int i = 0; i < 8; i++) {
        int idx = tid + i * 256;
        mskAll[idx] = mask[(size_t)b * TK + idx] ? -INFINITY : 0.f;
    }
    // ---- preload K tile 0 into Ks0 (group 0)
    {
        const unsigned ksm = sptr(Ks0);
#pragma unroll
        for (int j = 0; j < 8; j++) {
            int li = tid + j * 256;
            int r = li >> 4, c16 = li & 15;
            CP16(ksm + (r * 68 + c16 * 4) * 4, kbase + r * 64 + c16 * 4);
        }
        CP_COMMIT();
    }

    float acco[4][2][4] = {};
    float lsum[4][2] = {};
    const int perm0 = ((2 * tig) & 3) * 2 + (tig >> 1);   // store pos of col 2tig

    for (int nt = 0; nt < 16; nt++) {
        const int n0 = nt * 128;
        __syncthreads();   // prior PV done with Vs/Ps; Ks[(nt+1)&1] free

        // ---- issue V[nt] copy (single buffer) and K[nt+1] copy (double buf)
        {
            const unsigned vsm = sptr(Vsf);
#pragma unroll
            for (int j = 0; j < 8; j++) {
                int li = tid + j * 256;
                int r = li >> 4, c16 = li & 15;
                CP16(vsm + (r * 68 + c16 * 4) * 4, vbase + (size_t)(n0 + r) * 64 + c16 * 4);
            }
            CP_COMMIT();
        }
        if (nt < 15) {
            unsigned* Kn = ((nt + 1) & 1) ? Ks1 : Ks0;
            const unsigned ksm = sptr(Kn);
#pragma unroll
            for (int j = 0; j < 8; j++) {
                int li = tid + j * 256;
                int r = li >> 4, c16 = li & 15;
                CP16(ksm + (r * 68 + c16 * 4) * 4, kbase + (size_t)(n0 + 128 + r) * 64 + c16 * 4);
            }
            CP_COMMIT();
        }

        // ---- wait for K[nt] (leave newer groups in flight), publish
        if (nt < 15) asm volatile("cp.async.wait_group 2;");
        else         asm volatile("cp.async.wait_group 1;");
        __syncthreads();

        const float* Ksf = (const float*)(((nt & 1) ? Ks1 : Ks0));

        // ---- S = Q @ K^T
        float acc[4][4][4] = {};
#pragma unroll
        for (int kk = 0; kk < 64; kk += 8) {
            unsigned af[4][4], bf[4][2];
#pragma unroll
            for (int mi = 0; mi < 4; mi++) {
                int rb = wm * 64 + mi * 16;
                uint2 lo = *(const uint2*)&Qs[(rb + gid)     * 68 + kk + tig * 2];
                uint2 hi = *(const uint2*)&Qs[(rb + gid + 8) * 68 + kk + tig * 2];
                af[mi][0] = lo.x; af[mi][1] = hi.x; af[mi][2] = lo.y; af[mi][3] = hi.y;
            }
#pragma unroll
            for (int ni = 0; ni < 4; ni++) {
                int cb = wn * 32 + ni * 8;
                bf[ni][0] = f2tf(Ksf[(cb + gid) * 68 + kk + tig]);
                bf[ni][1] = f2tf(Ksf[(cb + gid) * 68 + kk + tig + 4]);
            }
#pragma unroll
            for (int mi = 0; mi < 4; mi++)
#pragma unroll
                for (int ni = 0; ni < 4; ni++) mma8(acc[mi][ni], af[mi], bf[ni]);
        }

        // ---- mask values for this thread's columns
        float mk[4][2];
#pragma unroll
        for (int ni = 0; ni < 4; ni++) {
            float2 mm = *(const float2*)&mskAll[n0 + wn * 32 + ni * 8 + 2 * tig];
            mk[ni][0] = mm.x; mk[ni][1] = mm.y;
        }

        // ---- E = exp(S+mask): write attn (unnormalized), rowsum, stage tf32
#pragma unroll
        for (int mi = 0; mi < 4; mi++) {
            int rb = wm * 64 + mi * 16;
#pragma unroll
            for (int hl = 0; hl < 2; hl++) {
                int row = rb + gid + hl * 8;
                float* arow = attn + ((size_t)bh * TQ + m0 + row) * TK + n0;
                float ls = 0.f;
#pragma unroll
                for (int ni = 0; ni < 4; ni++) {
                    int cb = wn * 32 + ni * 8;
                    float p0 = __expf(acc[mi][ni][hl * 2]     + mk[ni][0]);
                    float p1 = __expf(acc[mi][ni][hl * 2 + 1] + mk[ni][1]);
                    *(float2*)&arow[cb + 2 * tig] = make_float2(p0, p1);
                    unsigned* pp = &Ps[row * 132 + cb + perm0];
                    pp[0] = f2tf(p0); pp[2] = f2tf(p1);
                    ls += p0 + p1;
                }
                lsum[mi][hl] += ls;
            }
        }

        // ---- wait for V[nt], publish
        if (nt < 15) asm volatile("cp.async.wait_group 1;");
        else         asm volatile("cp.async.wait_group 0;");
        __syncthreads();

        // ---- O += E @ V  (k = 128 keys)
#pragma unroll
        for (int kk = 0; kk < 128; kk += 8) {
            unsigned af[4][4], bf[2][2];
#pragma unroll
            for (int mi = 0; mi < 4; mi++) {
                int rb = wm * 64 + mi * 16;
                uint2 lo = *(const uint2*)&Ps[(rb + gid)     * 132 + kk + tig * 2];
                uint2 hi = *(const uint2*)&Ps[(rb + gid + 8) * 132 + kk + tig * 2];
                af[mi][0] = lo.x; af[mi][1] = hi.x; af[mi][2] = lo.y; af[mi][3] = hi.y;
            }
#pragma unroll
            for (int ni = 0; ni < 2; ni++) {
                int cb = wn * 16 + ni * 8;
                bf[ni][0] = f2tf(Vsf[(kk + tig)     * 68 + cb + gid]);
                bf[ni][1] = f2tf(Vsf[(kk + tig + 4) * 68 + cb + gid]);
            }
#pragma unroll
            for (int mi = 0; mi < 4; mi++)
#pragma unroll
                for (int ni = 0; ni < 2; ni++) mma8(acco[mi][ni], af[mi], bf[ni]);
        }
    }

    // ---- rowsum reduce -> 1/l
    __syncthreads();
#pragma unroll
    for (int mi = 0; mi < 4; mi++)
#pragma unroll
        for (int hl = 0; hl < 2; hl++) {
            float v = lsum[mi][hl];
            v += __shfl_xor_sync(~0u, v, 1);
            v += __shfl_xor_sync(~0u, v, 2);
            if (tig == 0) red[wn * 128 + wm * 64 + mi * 16 + gid + hl * 8] = v;
        }
    __syncthreads();
    if (tid < 128) {
        float l = red[tid] + red[128 + tid] + red[256 + tid] + red[384 + tid];
        float inv = 1.f / l;
        sm_inv[tid] = inv;
        g_linv[(size_t)bh * TQ + m0 + tid] = inv;
    }
    __syncthreads();

    // ---- O normalize + store g_x [bh, t, d]
#pragma unroll
    for (int mi = 0; mi < 4; mi++)
#pragma unroll
        for (int hl = 0; hl < 2; hl++) {
            int row = wm * 64 + mi * 16 + gid + hl * 8;
            float inv = sm_inv[row];
#pragma unroll
            for (int ni = 0; ni < 2; ni++) {
                int c = wn * 16 + ni * 8 + tig * 2;
                *(float2*)&g_x[((size_t)bh * TQ + m0 + row) * DH + c] =
                    make_float2(acco[mi][ni][hl * 2] * inv,
                                acco[mi][ni][hl * 2 + 1] * inv);
            }
        }
}

// ---------------------------------------------------------------------------
// rescale: attn[row, :] *= g_linv[row]
// ---------------------------------------------------------------------------
__global__ __launch_bounds__(256)
void rescale_kernel(float* __restrict__ attn)
{
    const size_t row = blockIdx.x;
    const float inv = g_linv[row];
    float4* p = (float4*)(attn + row * (size_t)TK);
    const int tid = threadIdx.x;
#pragma unroll
    for (int i = 0; i < 2; i++) {
        float4 v = p[tid + i * 256];
        v.x *= inv; v.y *= inv; v.z *= inv; v.w *= inv;
        p[tid + i * 256] = v;
    }
}

// ---------------------------------------------------------------------------
extern "C" void kernel_launch(void* const* d_in, const int* in_sizes, int n_in,
                              void* d_out, int out_size)
{
    const float* query = (const float*)d_in[0];
    const float* key   = (const float*)d_in[1];
    const float* value = (const float*)d_in[2];
    const unsigned char* mask = (const unsigned char*)d_in[3];
    const float* Wq = (const float*)d_in[4];
    const float* bq = (const float*)d_in[5];
    const float* Wk = (const float*)d_in[6];
    const float* bk = (const float*)d_in[7];
    const float* Wv = (const float*)d_in[8];
    const float* bv = (const float*)d_in[9];
    const float* Wo = (const float*)d_in[10];
    const float* bo = (const float*)d_in[11];

    float* out_x = (float*)d_out;                       // [2048,4,1024]
    float* attn  = out_x + (size_t)TQ * BSZ * CDIM;     // [64,2048,2048]

    cudaFuncSetAttribute(attn_fused_kernel,
                         cudaFuncAttributeMaxDynamicSharedMemorySize, AT_SMEM);

    dim3 blk(256);
    qkv_proj_kernel<<<dim3(8, 64, 3), blk>>>(query, key, value,
                                             Wq, Wk, Wv, bq, bk, bv);
    attn_fused_kernel<<<dim3(16, 64), blk, AT_SMEM>>>(mask, attn);
    rescale_kernel<<<dim3(BH * TQ), blk>>>(attn);
    out_proj_kernel<<<dim3(8, 64), blk>>>(Wo, bo, out_x);
}

// round 6
// speedup vs baseline: 2.0982x; 1.1083x over previous
#include <cuda_runtime.h>
#include <math.h>

// ---------------------------------------------------------------------------
// Round 6: 512-thread fused attention (16 warps for latency coverage),
// cp.async double-buffered projections. tf32 mma.sync, fp32 accumulation.
// ---------------------------------------------------------------------------

constexpr int TQ  = 2048;
constexpr int TK  = 2048;
constexpr int BSZ = 4;
constexpr int CDIM = 1024;
constexpr int H   = 16;
constexpr int DH  = 64;
constexpr int BH  = BSZ * H;   // 64

__device__ __align__(16) float g_q[(size_t)BH * TQ * DH];
__device__ __align__(16) float g_k[(size_t)BH * TK * DH];
__device__ __align__(16) float g_v[(size_t)BH * TK * DH];
__device__ __align__(16) float g_x[(size_t)BH * TQ * DH];
__device__ float g_linv[(size_t)BH * TQ];

__device__ __forceinline__ unsigned f2tf(float x) {
    unsigned r; asm("cvt.rna.tf32.f32 %0, %1;" : "=r"(r) : "f"(x)); return r;
}
__device__ __forceinline__ void mma8(float* d, const unsigned* a, const unsigned* b) {
    asm volatile(
        "mma.sync.aligned.m16n8k8.row.col.f32.tf32.tf32.f32 "
        "{%0,%1,%2,%3},{%4,%5,%6,%7},{%8,%9},{%0,%1,%2,%3};"
        : "+f"(d[0]), "+f"(d[1]), "+f"(d[2]), "+f"(d[3])
        : "r"(a[0]), "r"(a[1]), "r"(a[2]), "r"(a[3]), "r"(b[0]), "r"(b[1]));
}
__device__ __forceinline__ unsigned sptr(const void* p) {
    return (unsigned)__cvta_generic_to_shared(p);
}
#define CP16(dst_u32, src_ptr) \
    asm volatile("cp.async.cg.shared.global [%0], [%1], 16;" :: "r"(dst_u32), "l"(src_ptr))
#define CP_COMMIT() asm volatile("cp.async.commit_group;")

// ---------------------------------------------------------------------------
// Projection GEMM core: 128x128 tile, k-step 32, double-buffered cp.async.
// Raw fp32 staged in smem; tf32 cvt at fragment load. 256 thr, 2 CTA/SM.
// ---------------------------------------------------------------------------
struct ProjSmem {
    float As[2][128 * 36];
    float Bs[2][32 * 136];
};

template<bool GATHER>
__device__ __forceinline__
void proj_body(const float* __restrict__ A, const float* __restrict__ W,
               const float* __restrict__ bias, float* __restrict__ dst,
               float scale, bool scatter, ProjSmem* sm,
               int m0, int n0)
{
    const int tid = threadIdx.x, lane = tid & 31, wid = tid >> 5;
    const int gid = lane >> 2, tig = lane & 3;
    const int wm = wid >> 2, wn = wid & 3;

    float acc[4][4][4] = {};

    // ---- issue copy of tile k-index 'it' into buffer it&1
    auto issue = [&](int it) {
        float* AsD = sm->As[it & 1];
        float* BsD = sm->Bs[it & 1];
        const unsigned asm_ = sptr(AsD), bsm_ = sptr(BsD);
        const int k0 = it * 32;
#pragma unroll
        for (int i = 0; i < 4; i++) {
            int li = tid + i * 256;
            int r = li >> 3, c = li & 7;
            if (!GATHER) {
                CP16(asm_ + (r * 36 + c * 4) * 4, &A[(size_t)(m0 + r) * CDIM + k0 + c * 4]);
            } else {
                int m = m0 + r, t = m >> 2, b = m & 3;
                int k = k0 + c * 4, h = k >> 6, d = k & 63;
                CP16(asm_ + (r * 36 + c * 4) * 4,
                     &g_x[(((size_t)(b * H + h)) * TQ + t) * DH + d]);
            }
        }
#pragma unroll
        for (int i = 0; i < 4; i++) {
            int li = tid + i * 256;
            int r = li >> 5, c = li & 31;
            CP16(bsm_ + (r * 136 + c * 4) * 4, &W[(size_t)(k0 + r) * CDIM + n0 + c * 4]);
        }
        CP_COMMIT();
    };

    issue(0);

    for (int it = 0; it < 32; it++) {
        if (it < 31) issue(it + 1);
        if (it < 31) asm volatile("cp.async.wait_group 1;");
        else         asm volatile("cp.async.wait_group 0;");
        __syncthreads();

        const float* AsF = sm->As[it & 1];
        const float* BsF = sm->Bs[it & 1];

#pragma unroll
        for (int kk = 0; kk < 32; kk += 8) {
            unsigned af[4][4], bf[4][2];
#pragma unroll
            for (int mi = 0; mi < 4; mi++) {
                int rb = wm * 64 + mi * 16;
                af[mi][0] = f2tf(AsF[(rb + gid)     * 36 + kk + tig]);
                af[mi][1] = f2tf(AsF[(rb + gid + 8) * 36 + kk + tig]);
                af[mi][2] = f2tf(AsF[(rb + gid)     * 36 + kk + tig + 4]);
                af[mi][3] = f2tf(AsF[(rb + gid + 8) * 36 + kk + tig + 4]);
            }
#pragma unroll
            for (int ni = 0; ni < 4; ni++) {
                int cb = wn * 32 + ni * 8;
                bf[ni][0] = f2tf(BsF[(kk + tig)     * 136 + cb + gid]);
                bf[ni][1] = f2tf(BsF[(kk + tig + 4) * 136 + cb + gid]);
            }
#pragma unroll
            for (int mi = 0; mi < 4; mi++)
#pragma unroll
                for (int ni = 0; ni < 4; ni++) mma8(acc[mi][ni], af[mi], bf[ni]);
        }
        __syncthreads();
    }

#pragma unroll
    for (int mi = 0; mi < 4; mi++)
#pragma unroll
        for (int hl = 0; hl < 2; hl++) {
            int m = m0 + wm * 64 + mi * 16 + gid + hl * 8;
#pragma unroll
            for (int ni = 0; ni < 4; ni++) {
                int n = n0 + wn * 32 + ni * 8 + tig * 2;
                float2 v;
                v.x = (acc[mi][ni][hl * 2 + 0] + bias[n + 0]) * scale;
                v.y = (acc[mi][ni][hl * 2 + 1] + bias[n + 1]) * scale;
                if (scatter) {
                    int t = m >> 2, b = m & 3, h = n >> 6, d = n & 63;
                    *(float2*)&dst[(((size_t)(b * H + h)) * TQ + t) * DH + d] = v;
                } else {
                    *(float2*)&dst[(size_t)m * CDIM + n] = v;
                }
            }
        }
}

__global__ __launch_bounds__(256, 2)
void qkv_proj_kernel(const float* __restrict__ Aq, const float* __restrict__ Ak,
                     const float* __restrict__ Av,
                     const float* __restrict__ Wq, const float* __restrict__ Wk,
                     const float* __restrict__ Wv,
                     const float* __restrict__ bq, const float* __restrict__ bk,
                     const float* __restrict__ bv)
{
    extern __shared__ char smraw[];
    ProjSmem* sm = (ProjSmem*)smraw;
    const int z = blockIdx.z;
    const float* A    = (z == 0) ? Aq : (z == 1) ? Ak : Av;
    const float* W    = (z == 0) ? Wq : (z == 1) ? Wk : Wv;
    const float* bias = (z == 0) ? bq : (z == 1) ? bk : bv;
    float* dst        = (z == 0) ? g_q : (z == 1) ? g_k : g_v;
    const float scale = (z == 0) ? 0.125f : 1.f;
    proj_body<false>(A, W, bias, dst, scale, true, sm,
                     blockIdx.y * 128, blockIdx.x * 128);
}

__global__ __launch_bounds__(256, 2)
void out_proj_kernel(const float* __restrict__ W, const float* __restrict__ bias,
                     float* __restrict__ Out)
{
    extern __shared__ char smraw[];
    ProjSmem* sm = (ProjSmem*)smraw;
    proj_body<true>(nullptr, W, bias, Out, 1.f, false, sm,
                    blockIdx.y * 128, blockIdx.x * 128);
}

constexpr int PROJ_SMEM = sizeof(ProjSmem);   // 71.7 KB

// ---------------------------------------------------------------------------
// attn_fused (512 threads, 16 warps): per (m-block 128, bh).
// Q resident tf32-perm. Per key tile: S=QK^T (K raw via cp.async dbl-buf),
// E=exp(S+mask) -> attn unnormalized + rowsum + Ps tf32-perm, O += E@V.
// Warp grid 4(m)x4(n): S warp tile 32x32, PV warp tile 32x16.
// smem u32 map: Qs 0..8704 | Ks[2] 8704..26112 | Vs 26112..34816 |
//   Ps 34816..51712 | mskAll 51712..53760 | red 53760..54272 | sm_inv ..54400
// ---------------------------------------------------------------------------
constexpr int AT_SMEM = 54400 * 4;   // 217.6 KB

__global__ __launch_bounds__(512, 1)
void attn_fused_kernel(const unsigned char* __restrict__ mask,
                       float* __restrict__ attn)
{
    extern __shared__ unsigned smem_u[];
    unsigned* Qs  = smem_u;
    unsigned* Ks0 = smem_u + 8704;                 // raw fp32 bits [n:128][d] s68
    unsigned* Ks1 = smem_u + 17408;
    float*    Vsf = (float*)(smem_u + 26112);      // raw fp32 [n:128][d] s68
    unsigned* Ps  = smem_u + 34816;                // [128][132] tf32 perm
    float* mskAll = (float*)(smem_u + 51712);      // [2048]
    float* red    = (float*)(smem_u + 53760);      // [4][128]
    float* sm_inv = (float*)(smem_u + 54272);

    const int tid = threadIdx.x, lane = tid & 31, wid = tid >> 5;
    const int gid = lane >> 2, tig = lane & 3;
    const int wm = wid >> 2, wn = wid & 3;         // 4 x 4 warps
    const int m0 = blockIdx.x * 128, bh = blockIdx.y, b = bh >> 4;

    const float* kbase = g_k + (size_t)bh * TK * DH;
    const float* vbase = g_v + (size_t)bh * TK * DH;

    // ---- Q -> smem tf32, permuted cols: k -> (k&~7) + (k&3)*2 + ((k>>2)&1)
#pragma unroll
    for (int i = 0; i < 4; i++) {
        int li = tid + i * 512;
        int r = li >> 4, c = li & 15;
        float4 a = *(const float4*)&g_q[((size_t)bh * TQ + m0 + r) * DH + c * 4];
        unsigned* q = &Qs[r * 68 + (c >> 1) * 8 + (c & 1)];
        q[0] = f2tf(a.x); q[2] = f2tf(a.y); q[4] = f2tf(a.z); q[6] = f2tf(a.w);
    }
    // ---- full mask row
#pragma unroll
    for (int i = 0; i < 4; i++) {
        int idx = tid + i * 512;
        mskAll[idx] = mask[(size_t)b * TK + idx] ? -INFINITY : 0.f;
    }
    // ---- preload K tile 0
    {
        const unsigned ksm = sptr(Ks0);
#pragma unroll
        for (int j = 0; j < 4; j++) {
            int li = tid + j * 512;
            int r = li >> 4, c16 = li & 15;
            CP16(ksm + (r * 68 + c16 * 4) * 4, kbase + r * 64 + c16 * 4);
        }
        CP_COMMIT();
    }

    float acco[2][2][4] = {};
    float lsum[2][2] = {};
    const int perm0 = ((2 * tig) & 3) * 2 + (tig >> 1);

    for (int nt = 0; nt < 16; nt++) {
        const int n0 = nt * 128;
        __syncthreads();   // prior PV done with Vs/Ps; Ks[(nt+1)&1] free

        // ---- issue V[nt] and K[nt+1] copies
        {
            const unsigned vsm = sptr(Vsf);
#pragma unroll
            for (int j = 0; j < 4; j++) {
                int li = tid + j * 512;
                int r = li >> 4, c16 = li & 15;
                CP16(vsm + (r * 68 + c16 * 4) * 4, vbase + (size_t)(n0 + r) * 64 + c16 * 4);
            }
            CP_COMMIT();
        }
        if (nt < 15) {
            unsigned* Kn = ((nt + 1) & 1) ? Ks1 : Ks0;
            const unsigned ksm = sptr(Kn);
#pragma unroll
            for (int j = 0; j < 4; j++) {
                int li = tid + j * 512;
                int r = li >> 4, c16 = li & 15;
                CP16(ksm + (r * 68 + c16 * 4) * 4,
                     kbase + (size_t)(n0 + 128 + r) * 64 + c16 * 4);
            }
            CP_COMMIT();
        }

        if (nt < 15) asm volatile("cp.async.wait_group 2;");
        else         asm volatile("cp.async.wait_group 1;");
        __syncthreads();

        const float* Ksf = (const float*)((nt & 1) ? Ks1 : Ks0);

        // ---- S = Q @ K^T   (warp tile 32m x 32n)
        float acc[2][4][4] = {};
#pragma unroll
        for (int kk = 0; kk < 64; kk += 8) {
            unsigned af[2][4], bf[4][2];
#pragma unroll
            for (int mi = 0; mi < 2; mi++) {
                int rb = wm * 32 + mi * 16;
                uint2 lo = *(const uint2*)&Qs[(rb + gid)     * 68 + kk + tig * 2];
                uint2 hi = *(const uint2*)&Qs[(rb + gid + 8) * 68 + kk + tig * 2];
                af[mi][0] = lo.x; af[mi][1] = hi.x; af[mi][2] = lo.y; af[mi][3] = hi.y;
            }
#pragma unroll
            for (int ni = 0; ni < 4; ni++) {
                int cb = wn * 32 + ni * 8;
                bf[ni][0] = f2tf(Ksf[(cb + gid) * 68 + kk + tig]);
                bf[ni][1] = f2tf(Ksf[(cb + gid) * 68 + kk + tig + 4]);
            }
#pragma unroll
            for (int mi = 0; mi < 2; mi++)
#pragma unroll
                for (int ni = 0; ni < 4; ni++) mma8(acc[mi][ni], af[mi], bf[ni]);
        }

        // ---- mask for this thread's columns
        float mk[4][2];
#pragma unroll
        for (int ni = 0; ni < 4; ni++) {
            float2 mm = *(const float2*)&mskAll[n0 + wn * 32 + ni * 8 + 2 * tig];
            mk[ni][0] = mm.x; mk[ni][1] = mm.y;
        }

        // ---- E = exp(S+mask): attn write (unnormalized), rowsum, Ps stage
#pragma unroll
        for (int mi = 0; mi < 2; mi++) {
            int rb = wm * 32 + mi * 16;
#pragma unroll
            for (int hl = 0; hl < 2; hl++) {
                int row = rb + gid + hl * 8;
                float* arow = attn + ((size_t)bh * TQ + m0 + row) * TK + n0;
                float ls = 0.f;
#pragma unroll
                for (int ni = 0; ni < 4; ni++) {
                    int cb = wn * 32 + ni * 8;
                    float p0 = __expf(acc[mi][ni][hl * 2]     + mk[ni][0]);
                    float p1 = __expf(acc[mi][ni][hl * 2 + 1] + mk[ni][1]);
                    *(float2*)&arow[cb + 2 * tig] = make_float2(p0, p1);
                    unsigned* pp = &Ps[row * 132 + cb + perm0];
                    pp[0] = f2tf(p0); pp[2] = f2tf(p1);
                    ls += p0 + p1;
                }
                lsum[mi][hl] += ls;
            }
        }

        if (nt < 15) asm volatile("cp.async.wait_group 1;");
        else         asm volatile("cp.async.wait_group 0;");
        __syncthreads();

        // ---- O += E @ V   (warp tile 32m x 16n, k = 128)
#pragma unroll
        for (int kk = 0; kk < 128; kk += 8) {
            unsigned af[2][4], bf[2][2];
#pragma unroll
            for (int mi = 0; mi < 2; mi++) {
                int rb = wm * 32 + mi * 16;
                uint2 lo = *(const uint2*)&Ps[(rb + gid)     * 132 + kk + tig * 2];
                uint2 hi = *(const uint2*)&Ps[(rb + gid + 8) * 132 + kk + tig * 2];
                af[mi][0] = lo.x; af[mi][1] = hi.x; af[mi][2] = lo.y; af[mi][3] = hi.y;
            }
#pragma unroll
            for (int ni = 0; ni < 2; ni++) {
                int cb = wn * 16 + ni * 8;
                bf[ni][0] = f2tf(Vsf[(kk + tig)     * 68 + cb + gid]);
                bf[ni][1] = f2tf(Vsf[(kk + tig + 4) * 68 + cb + gid]);
            }
#pragma unroll
            for (int mi = 0; mi < 2; mi++)
#pragma unroll
                for (int ni = 0; ni < 2; ni++) mma8(acco[mi][ni], af[mi], bf[ni]);
        }
    }

    // ---- rowsum reduce -> 1/l
    __syncthreads();
#pragma unroll
    for (int mi = 0; mi < 2; mi++)
#pragma unroll
        for (int hl = 0; hl < 2; hl++) {
            float v = lsum[mi][hl];
            v += __shfl_xor_sync(~0u, v, 1);
            v += __shfl_xor_sync(~0u, v, 2);
            if (tig == 0) red[wn * 128 + wm * 32 + mi * 16 + gid + hl * 8] = v;
        }
    __syncthreads();
    if (tid < 128) {
        float l = red[tid] + red[128 + tid] + red[256 + tid] + red[384 + tid];
        float inv = 1.f / l;
        sm_inv[tid] = inv;
        g_linv[(size_t)bh * TQ + m0 + tid] = inv;
    }
    __syncthreads();

    // ---- O normalize + store g_x [bh, t, d]
#pragma unroll
    for (int mi = 0; mi < 2; mi++)
#pragma unroll
        for (int hl = 0; hl < 2; hl++) {
            int row = wm * 32 + mi * 16 + gid + hl * 8;
            float inv = sm_inv[row];
#pragma unroll
            for (int ni = 0; ni < 2; ni++) {
                int c = wn * 16 + ni * 8 + tig * 2;
                *(float2*)&g_x[((size_t)bh * TQ + m0 + row) * DH + c] =
                    make_float2(acco[mi][ni][hl * 2] * inv,
                                acco[mi][ni][hl * 2 + 1] * inv);
            }
        }
}

// ---------------------------------------------------------------------------
// rescale: attn[row, :] *= g_linv[row]
// ---------------------------------------------------------------------------
__global__ __launch_bounds__(256)
void rescale_kernel(float* __restrict__ attn)
{
    const size_t row = blockIdx.x;
    const float inv = g_linv[row];
    float4* p = (float4*)(attn + row * (size_t)TK);
    const int tid = threadIdx.x;
#pragma unroll
    for (int i = 0; i < 2; i++) {
        float4 v = p[tid + i * 256];
        v.x *= inv; v.y *= inv; v.z *= inv; v.w *= inv;
        p[tid + i * 256] = v;
    }
}

// ---------------------------------------------------------------------------
extern "C" void kernel_launch(void* const* d_in, const int* in_sizes, int n_in,
                              void* d_out, int out_size)
{
    const float* query = (const float*)d_in[0];
    const float* key   = (const float*)d_in[1];
    const float* value = (const float*)d_in[2];
    const unsigned char* mask = (const unsigned char*)d_in[3];
    const float* Wq = (const float*)d_in[4];
    const float* bq = (const float*)d_in[5];
    const float* Wk = (const float*)d_in[6];
    const float* bk = (const float*)d_in[7];
    const float* Wv = (const float*)d_in[8];
    const float* bv = (const float*)d_in[9];
    const float* Wo = (const float*)d_in[10];
    const float* bo = (const float*)d_in[11];

    float* out_x = (float*)d_out;                       // [2048,4,1024]
    float* attn  = out_x + (size_t)TQ * BSZ * CDIM;     // [64,2048,2048]

    cudaFuncSetAttribute(attn_fused_kernel,
                         cudaFuncAttributeMaxDynamicSharedMemorySize, AT_SMEM);
    cudaFuncSetAttribute(qkv_proj_kernel,
                         cudaFuncAttributeMaxDynamicSharedMemorySize, PROJ_SMEM);
    cudaFuncSetAttribute(out_proj_kernel,
                         cudaFuncAttributeMaxDynamicSharedMemorySize, PROJ_SMEM);

    qkv_proj_kernel<<<dim3(8, 64, 3), 256, PROJ_SMEM>>>(query, key, value,
                                                        Wq, Wk, Wv, bq, bk, bv);
    attn_fused_kernel<<<dim3(16, 64), 512, AT_SMEM>>>(mask, attn);
    rescale_kernel<<<dim3(BH * TQ), 256>>>(attn);
    out_proj_kernel<<<dim3(8, 64), 256, PROJ_SMEM>>>(Wo, bo, out_x);
}